// round 15
// baseline (speedup 1.0000x reference)
#include <cuda_runtime.h>
#include <cuda_bf16.h>

// Problem constants (from reference): B=64, N=512, T=2048.
// Data ranges: mel_lens in [1024, 2048], seq_lens in [256, 512].
#define GAL_B 64
#define GAL_N 512
#define GAL_T 2048
#define GAL_ROWS   (GAL_B * GAL_N)        // 32768
#define GAL_RPB    32                     // rows per block (long pipeline)
#define GAL_BLOCKS (GAL_ROWS / GAL_RPB)   // 1024
#define GAL_GRP    2                      // rows per pipeline group (reg diet)
#define GAL_ROW_U2 (GAL_T / 4)            // 512 ulonglong2 per row

typedef unsigned long long u64;

// Scratch (allocation-free: __device__ globals).
__device__ float        g_gal_partials[GAL_BLOCKS];
__device__ unsigned int g_gal_count = 0;   // reset by last block each launch

// ---- sm_103a packed-f32 helpers -------------------------------------------
__device__ __forceinline__ float ex2a(float x) {
    float r; asm("ex2.approx.f32 %0, %1;" : "=f"(r) : "f"(x)); return r;
}
__device__ __forceinline__ u64 pack2(float lo, float hi) {
    u64 r; asm("mov.b64 %0, {%1, %2};" : "=l"(r) : "f"(lo), "f"(hi)); return r;
}
__device__ __forceinline__ void unpack2(u64 v, float& lo, float& hi) {
    asm("mov.b64 {%0, %1}, %2;" : "=f"(lo), "=f"(hi) : "l"(v));
}
__device__ __forceinline__ u64 mul2(u64 a, u64 b) {
    u64 r; asm("mul.rn.f32x2 %0, %1, %2;" : "=l"(r) : "l"(a), "l"(b)); return r;
}
__device__ __forceinline__ u64 add2(u64 a, u64 b) {
    u64 r; asm("add.rn.f32x2 %0, %1, %2;" : "=l"(r) : "l"(a), "l"(b)); return r;
}
__device__ __forceinline__ u64 fma2(u64 a, u64 b, u64 c) {
    u64 r; asm("fma.rn.f32x2 %0, %1, %2, %3;" : "=l"(r) : "l"(a), "l"(b), "l"(c)); return r;
}

// ---------------------------------------------------------------------------
// 1024 static blocks x 256 threads; R12's 32-row pipeline with two changes:
//  * GRP=2 (data buffer 16 regs, total <=64) so FOUR CTAs fit per SM:
//    32 warps/SM hide the block-start bubbles that capped R12 at 63% DRAM.
//  * LPT block map: b = bid & 63, n0 = (bid>>6)*32. The first 512 bids
//    (n0 < 256 <= min sl) are guaranteed full-length and schedule first;
//    variable/dead blocks schedule last and fill the tail.
//
// Per block: 16 groups of 2 rows, pipelined:
//    compute A(g) -> issue A(g+1) -> compute B(g) -> issue B(g+1)
// Thread tid owns t in [4*tid,4*tid+4) (chunk A: always live, mel>=1024) and
// [1024+4*tid,...) (chunk B: mask premultiplied into the eB chain; raw part
// masked via fma2). Weight w = 1 - exp2(-u^2); Gaussian recurrence in n:
//    e <- e*r, r <- r*c, c = exp2(-2 d^2), d = s/sl
// One raw + one exp f32x2 accumulator. Last-finishing block performs the
// final deterministic double reduction over the 1024 per-block partials.
// ---------------------------------------------------------------------------
__global__ void __launch_bounds__(256, 4)
gal_main_kernel(const float* __restrict__ A,
                const float* __restrict__ g_ptr,
                const int*   __restrict__ mel_lens,
                const int*   __restrict__ seq_lens,
                float*       __restrict__ out)
{
    const int tid = threadIdx.x;

    // ---- LPT tile map: low n0 first, batch-fast ----
    const int b    = blockIdx.x & 63;
    const int n0   = (blockIdx.x >> 6) << 5;     // 0,32,...,480
    const int row0 = (b << 9) + n0;

    const int   sl = seq_lens[b];
    const int   ml = mel_lens[b];
    const float g  = *g_ptr;

    const float s      = sqrtf(1.4426950408889634f / (2.0f * g * g));
    const float xscale = s / (float)sl;    // u row-step d
    const float tscale = s / (float)ml;

    const int  tA   = tid * 4;             // < 1024 <= ml : always live
    const int  tB   = 1024 + tid * 4;
    const bool anyB = (tB < ml);

    float sum = 0.0f;

    const int Lraw = sl - n0;
    const int L    = (Lraw > GAL_RPB) ? GAL_RPB : Lraw;   // live rows, may be <=0
    const int G    = (L > 0) ? (L >> 1) : 0;              // full 2-row groups

    if (G > 0) {
        // ---- chain init at n = n0 (masks premultiplied into eB) ----
        const float dx  = xscale;
        const float cc  = ex2a(-2.0f * dx * dx);
        const u64   c2  = pack2(cc, cc);
        const float n0f = (float)n0;

        float mk[4];
        #pragma unroll
        for (int k = 0; k < 4; ++k) mk[k] = (tB + k < ml) ? 1.0f : 0.0f;
        const u64 mB01 = pack2(mk[0], mk[1]);
        const u64 mB23 = pack2(mk[2], mk[3]);

        u64 eA[2], rA[2], eB[2], rB[2];
        #pragma unroll
        for (int p = 0; p < 2; ++p) {
            float u0 = n0f * xscale - (float)(tA + 2*p    ) * tscale;
            float u1 = n0f * xscale - (float)(tA + 2*p + 1) * tscale;
            eA[p] = pack2(ex2a(-u0 * u0), ex2a(-u1 * u1));
            rA[p] = pack2(ex2a(fmaf(-2.0f * dx, u0, -dx * dx)),
                          ex2a(fmaf(-2.0f * dx, u1, -dx * dx)));
            float v0 = n0f * xscale - (float)(tB + 2*p    ) * tscale;
            float v1 = n0f * xscale - (float)(tB + 2*p + 1) * tscale;
            eB[p] = pack2(mk[2*p]   * ex2a(-v0 * v0),
                          mk[2*p+1] * ex2a(-v1 * v1));
            rB[p] = pack2(ex2a(fmaf(-2.0f * dx, v0, -dx * dx)),
                          ex2a(fmaf(-2.0f * dx, v1, -dx * dx)));
        }

        u64 accR = 0ull, accE = 0ull;      // (0.0f, 0.0f) packed

        const ulonglong2* __restrict__ pA =
            (const ulonglong2*)(A + ((size_t)row0 << 11)) + tid;

        // ---- prologue: load group 0 (2 rows A, 2 rows B) ----
        ulonglong2 va[GAL_GRP], vb[GAL_GRP];
        #pragma unroll
        for (int r = 0; r < GAL_GRP; ++r) va[r] = pA[r * GAL_ROW_U2];
        if (anyB) {
            #pragma unroll
            for (int r = 0; r < GAL_GRP; ++r) vb[r] = pA[r * GAL_ROW_U2 + 256];
        }

        // ---- steady-state pipeline over G groups ----
        int gi = 0;
        for (;;) {
            const bool more = (gi + 1 < G);

            // compute A(gi); vb(gi) already in flight
            #pragma unroll
            for (int r = 0; r < GAL_GRP; ++r) {
                accR  = add2(accR, va[r].x);
                accR  = add2(accR, va[r].y);
                accE  = fma2(eA[0], va[r].x, accE);
                accE  = fma2(eA[1], va[r].y, accE);
                eA[0] = mul2(eA[0], rA[0]);  rA[0] = mul2(rA[0], c2);
                eA[1] = mul2(eA[1], rA[1]);  rA[1] = mul2(rA[1], c2);
            }

            // issue A(gi+1) into the just-consumed buffer
            if (more) {
                #pragma unroll
                for (int r = 0; r < GAL_GRP; ++r)
                    va[r] = pA[(r + GAL_GRP) * GAL_ROW_U2];
            }

            // compute B(gi); va(gi+1) in flight
            if (anyB) {
                #pragma unroll
                for (int r = 0; r < GAL_GRP; ++r) {
                    accR  = fma2(mB01, vb[r].x, accR);
                    accR  = fma2(mB23, vb[r].y, accR);
                    accE  = fma2(eB[0], vb[r].x, accE);
                    accE  = fma2(eB[1], vb[r].y, accE);
                    eB[0] = mul2(eB[0], rB[0]);  rB[0] = mul2(rB[0], c2);
                    eB[1] = mul2(eB[1], rB[1]);  rB[1] = mul2(rB[1], c2);
                }
                if (more) {
                    #pragma unroll
                    for (int r = 0; r < GAL_GRP; ++r)
                        vb[r] = pA[(r + GAL_GRP) * GAL_ROW_U2 + 256];
                }
            }

            if (!more) break;
            pA += GAL_GRP * GAL_ROW_U2;
            ++gi;
        }

        float lo, hi;
        unpack2(accR, lo, hi);  sum  = lo + hi;
        unpack2(accE, lo, hi);  sum -= lo + hi;
    }

    // ---- scalar tail: rows 2G .. L-1 (0..1 rows; boundary blocks only) ----
    if (L > 2 * G) {
        float tsA[4], tsB[4], mB[4];
        #pragma unroll
        for (int k = 0; k < 4; ++k) {
            tsA[k] = (float)(tA + k) * tscale;
            tsB[k] = (float)(tB + k) * tscale;
            mB[k]  = (tB + k < ml) ? 1.0f : 0.0f;
        }
        const float4* __restrict__ base = (const float4*)(A + ((size_t)row0 << 11));
        for (int r = 2 * G; r < L; ++r) {
            const float xs = (float)(n0 + r) * xscale;
            const float4* __restrict__ Arow = base + r * (GAL_T / 4);
            {
                const float4 a = Arow[tid];
                const float av[4] = {a.x, a.y, a.z, a.w};
                #pragma unroll
                for (int k = 0; k < 4; ++k) {
                    const float u = xs - tsA[k];
                    sum = fmaf(1.0f - ex2a(-u * u), av[k], sum);
                }
            }
            if (anyB) {
                const float4 a = Arow[tid + 256];
                const float av[4] = {a.x, a.y, a.z, a.w};
                #pragma unroll
                for (int k = 0; k < 4; ++k) {
                    const float u = xs - tsB[k];
                    sum = fmaf((1.0f - ex2a(-u * u)) * mB[k], av[k], sum);
                }
            }
        }
    }
    // (blocks with n0 >= sl fall through with sum = 0)

    // ---- block reduction (deterministic) ----
    #pragma unroll
    for (int o = 16; o > 0; o >>= 1)
        sum += __shfl_xor_sync(0xffffffffu, sum, o);

    __shared__ float warp_sums[8];
    if ((tid & 31) == 0) warp_sums[tid >> 5] = sum;
    __syncthreads();

    __shared__ bool is_last;
    if (tid == 0) {
        float v = warp_sums[0];
        #pragma unroll
        for (int w = 1; w < 8; ++w) v += warp_sums[w];
        g_gal_partials[blockIdx.x] = v;
        __threadfence();                                  // publish partial
        unsigned int old = atomicAdd(&g_gal_count, 1u);
        is_last = (old == GAL_BLOCKS - 1);
    }
    __syncthreads();

    // ---- last block: final deterministic reduction in double ----
    if (is_last) {
        __threadfence();                                  // acquire partials
        const float4* __restrict__ p4 = (const float4*)g_gal_partials;
        double sd = 0.0;
        {                                                 // 1 float4 per thread
            const float4 p = p4[tid];
            sd += ((double)p.x + (double)p.y) + ((double)p.z + (double)p.w);
        }
        __shared__ double sh[256];
        sh[tid] = sd;
        __syncthreads();
        #pragma unroll
        for (int stride = 128; stride > 0; stride >>= 1) {
            if (tid < stride) sh[tid] += sh[tid + stride];
            __syncthreads();
        }
        if (tid == 0) {
            *out = (float)(sh[0] / (double)GAL_B);
            g_gal_count = 0;                              // reset for replay
        }
    }
}

// ---------------------------------------------------------------------------
// kernel_launch: inputs per metadata order:
//   d_in[0] = A        float32  [B*N*T]
//   d_in[1] = g        float32  [1]
//   d_in[2] = mel_lens int32    [B]
//   d_in[3] = seq_lens int32    [B]
// d_out: float32 [1]
// ---------------------------------------------------------------------------
extern "C" void kernel_launch(void* const* d_in, const int* in_sizes, int n_in,
                              void* d_out, int out_size)
{
    const float* A        = (const float*)d_in[0];
    const float* g        = (const float*)d_in[1];
    const int*   mel_lens = (const int*)d_in[2];
    const int*   seq_lens = (const int*)d_in[3];
    float*       out      = (float*)d_out;

    gal_main_kernel<<<GAL_BLOCKS, 256>>>(A, g, mel_lens, seq_lens, out);
}

// round 16
// speedup vs baseline: 1.1124x; 1.1124x over previous
#include <cuda_runtime.h>
#include <cuda_bf16.h>

// Problem constants (from reference): B=64, N=512, T=2048.
// Data ranges: mel_lens in [1024, 2048], seq_lens in [256, 512].
#define GAL_B 64
#define GAL_N 512
#define GAL_T 2048
#define GAL_ROWS   (GAL_B * GAL_N)        // 32768
#define GAL_RPB    32                     // rows per block (long pipeline)
#define GAL_BLOCKS (GAL_ROWS / GAL_RPB)   // 1024
#define GAL_GRP    4                      // rows per pipeline group (R12 best)
#define GAL_ROW_U2 (GAL_T / 4)            // 512 ulonglong2 per row

typedef unsigned long long u64;

// Scratch (allocation-free: __device__ globals).
__device__ float        g_gal_partials[GAL_BLOCKS];
__device__ unsigned int g_gal_count = 0;   // reset by last block each launch

// ---- sm_103a packed-f32 helpers -------------------------------------------
__device__ __forceinline__ float ex2a(float x) {
    float r; asm("ex2.approx.f32 %0, %1;" : "=f"(r) : "f"(x)); return r;
}
__device__ __forceinline__ u64 pack2(float lo, float hi) {
    u64 r; asm("mov.b64 %0, {%1, %2};" : "=l"(r) : "f"(lo), "f"(hi)); return r;
}
__device__ __forceinline__ void unpack2(u64 v, float& lo, float& hi) {
    asm("mov.b64 {%0, %1}, %2;" : "=f"(lo), "=f"(hi) : "l"(v));
}
__device__ __forceinline__ u64 mul2(u64 a, u64 b) {
    u64 r; asm("mul.rn.f32x2 %0, %1, %2;" : "=l"(r) : "l"(a), "l"(b)); return r;
}
__device__ __forceinline__ u64 add2(u64 a, u64 b) {
    u64 r; asm("add.rn.f32x2 %0, %1, %2;" : "=l"(r) : "l"(a), "l"(b)); return r;
}
__device__ __forceinline__ u64 fma2(u64 a, u64 b, u64 c) {
    u64 r; asm("fma.rn.f32x2 %0, %1, %2, %3;" : "=l"(r) : "l"(a), "l"(b), "l"(c)); return r;
}

// ---------------------------------------------------------------------------
// EXACT R12 pipeline (best: 33.3us / 63% DRAM) + two local changes:
//  * LPT block map: b = bid & 63, n0 = (bid>>6)*32. The first 512 bids
//    (n0 < 256 <= min sl) are guaranteed full-length and schedule FIRST;
//    variable/dead blocks schedule last and fill the tail wave.
//  * Group-0 loads issued BEFORE the EX2 chain init, so the per-block
//    startup DRAM latency overlaps the ~300cyc of MUFU init work.
//
// 1024 blocks x 256 threads, 32 rows/block, pipeline over 8 groups of 4:
//    compute A(g) -> issue A(g+1) -> compute B(g) -> issue B(g+1)
// Thread tid owns t in [4*tid,4*tid+4) (chunk A: always live, mel>=1024) and
// [1024+4*tid,...) (chunk B: mask premultiplied into the eB chain).
// Weight w = 1 - exp2(-u^2); Gaussian recurrence in n:
//    e <- e*r, r <- r*c, c = exp2(-2 d^2), d = s/sl
// One raw + one exp f32x2 accumulator. Last-finishing block performs the
// final deterministic double reduction over the 1024 per-block partials.
// ---------------------------------------------------------------------------
__global__ void __launch_bounds__(256, 3)
gal_main_kernel(const float* __restrict__ A,
                const float* __restrict__ g_ptr,
                const int*   __restrict__ mel_lens,
                const int*   __restrict__ seq_lens,
                float*       __restrict__ out)
{
    const int tid = threadIdx.x;

    // ---- LPT tile map: low n0 first, batch-fast ----
    const int b    = blockIdx.x & 63;
    const int n0   = (blockIdx.x >> 6) << 5;     // 0,32,...,480
    const int row0 = (b << 9) + n0;

    const int   sl = seq_lens[b];
    const int   ml = mel_lens[b];
    const float g  = *g_ptr;

    const float s      = sqrtf(1.4426950408889634f / (2.0f * g * g));
    const float xscale = s / (float)sl;    // u row-step d
    const float tscale = s / (float)ml;

    const int  tA   = tid * 4;             // < 1024 <= ml : always live
    const int  tB   = 1024 + tid * 4;
    const bool anyB = (tB < ml);

    float sum = 0.0f;

    const int Lraw = sl - n0;
    const int L    = (Lraw > GAL_RPB) ? GAL_RPB : Lraw;   // live rows, may be <=0
    const int G    = (L > 0) ? (L >> 2) : 0;              // full 4-row groups

    if (G > 0) {
        const ulonglong2* __restrict__ pA =
            (const ulonglong2*)(A + ((size_t)row0 << 11)) + tid;

        // ---- prologue loads FIRST: group 0 (4 rows A, 4 rows B) ----
        ulonglong2 va[GAL_GRP], vb[GAL_GRP];
        #pragma unroll
        for (int r = 0; r < GAL_GRP; ++r) va[r] = pA[r * GAL_ROW_U2];
        if (anyB) {
            #pragma unroll
            for (int r = 0; r < GAL_GRP; ++r) vb[r] = pA[r * GAL_ROW_U2 + 256];
        }

        // ---- chain init at n = n0 (overlaps the loads above) ----
        const float dx  = xscale;
        const float cc  = ex2a(-2.0f * dx * dx);
        const u64   c2  = pack2(cc, cc);
        const float n0f = (float)n0;

        float mk[4];
        #pragma unroll
        for (int k = 0; k < 4; ++k) mk[k] = (tB + k < ml) ? 1.0f : 0.0f;
        const u64 mB01 = pack2(mk[0], mk[1]);
        const u64 mB23 = pack2(mk[2], mk[3]);

        u64 eA[2], rA[2], eB[2], rB[2];
        #pragma unroll
        for (int p = 0; p < 2; ++p) {
            float u0 = n0f * xscale - (float)(tA + 2*p    ) * tscale;
            float u1 = n0f * xscale - (float)(tA + 2*p + 1) * tscale;
            eA[p] = pack2(ex2a(-u0 * u0), ex2a(-u1 * u1));
            rA[p] = pack2(ex2a(fmaf(-2.0f * dx, u0, -dx * dx)),
                          ex2a(fmaf(-2.0f * dx, u1, -dx * dx)));
            float v0 = n0f * xscale - (float)(tB + 2*p    ) * tscale;
            float v1 = n0f * xscale - (float)(tB + 2*p + 1) * tscale;
            eB[p] = pack2(mk[2*p]   * ex2a(-v0 * v0),
                          mk[2*p+1] * ex2a(-v1 * v1));
            rB[p] = pack2(ex2a(fmaf(-2.0f * dx, v0, -dx * dx)),
                          ex2a(fmaf(-2.0f * dx, v1, -dx * dx)));
        }

        u64 accR = 0ull, accE = 0ull;      // (0.0f, 0.0f) packed

        // ---- steady-state pipeline over G groups ----
        int gi = 0;
        for (;;) {
            const bool more = (gi + 1 < G);

            // compute A(gi); vb(gi) already in flight
            #pragma unroll
            for (int r = 0; r < GAL_GRP; ++r) {
                accR  = add2(accR, va[r].x);
                accR  = add2(accR, va[r].y);
                accE  = fma2(eA[0], va[r].x, accE);
                accE  = fma2(eA[1], va[r].y, accE);
                eA[0] = mul2(eA[0], rA[0]);  rA[0] = mul2(rA[0], c2);
                eA[1] = mul2(eA[1], rA[1]);  rA[1] = mul2(rA[1], c2);
            }

            // issue A(gi+1) into the just-consumed buffer
            if (more) {
                #pragma unroll
                for (int r = 0; r < GAL_GRP; ++r)
                    va[r] = pA[(r + GAL_GRP) * GAL_ROW_U2];
            }

            // compute B(gi); va(gi+1) in flight
            if (anyB) {
                #pragma unroll
                for (int r = 0; r < GAL_GRP; ++r) {
                    accR  = fma2(mB01, vb[r].x, accR);
                    accR  = fma2(mB23, vb[r].y, accR);
                    accE  = fma2(eB[0], vb[r].x, accE);
                    accE  = fma2(eB[1], vb[r].y, accE);
                    eB[0] = mul2(eB[0], rB[0]);  rB[0] = mul2(rB[0], c2);
                    eB[1] = mul2(eB[1], rB[1]);  rB[1] = mul2(rB[1], c2);
                }
                if (more) {
                    #pragma unroll
                    for (int r = 0; r < GAL_GRP; ++r)
                        vb[r] = pA[(r + GAL_GRP) * GAL_ROW_U2 + 256];
                }
            }

            if (!more) break;
            pA += GAL_GRP * GAL_ROW_U2;
            ++gi;
        }

        float lo, hi;
        unpack2(accR, lo, hi);  sum  = lo + hi;
        unpack2(accE, lo, hi);  sum -= lo + hi;
    }

    // ---- scalar tail: rows 4G .. L-1 (0..3 rows; boundary blocks only) ----
    if (L > 4 * G) {
        float tsA[4], tsB[4], mB[4];
        #pragma unroll
        for (int k = 0; k < 4; ++k) {
            tsA[k] = (float)(tA + k) * tscale;
            tsB[k] = (float)(tB + k) * tscale;
            mB[k]  = (tB + k < ml) ? 1.0f : 0.0f;
        }
        const float4* __restrict__ base = (const float4*)(A + ((size_t)row0 << 11));
        for (int r = 4 * G; r < L; ++r) {
            const float xs = (float)(n0 + r) * xscale;
            const float4* __restrict__ Arow = base + r * (GAL_T / 4);
            {
                const float4 a = Arow[tid];
                const float av[4] = {a.x, a.y, a.z, a.w};
                #pragma unroll
                for (int k = 0; k < 4; ++k) {
                    const float u = xs - tsA[k];
                    sum = fmaf(1.0f - ex2a(-u * u), av[k], sum);
                }
            }
            if (anyB) {
                const float4 a = Arow[tid + 256];
                const float av[4] = {a.x, a.y, a.z, a.w};
                #pragma unroll
                for (int k = 0; k < 4; ++k) {
                    const float u = xs - tsB[k];
                    sum = fmaf((1.0f - ex2a(-u * u)) * mB[k], av[k], sum);
                }
            }
        }
    }
    // (blocks with n0 >= sl fall through with sum = 0)

    // ---- block reduction (deterministic) ----
    #pragma unroll
    for (int o = 16; o > 0; o >>= 1)
        sum += __shfl_xor_sync(0xffffffffu, sum, o);

    __shared__ float warp_sums[8];
    if ((tid & 31) == 0) warp_sums[tid >> 5] = sum;
    __syncthreads();

    __shared__ bool is_last;
    if (tid == 0) {
        float v = warp_sums[0];
        #pragma unroll
        for (int w = 1; w < 8; ++w) v += warp_sums[w];
        g_gal_partials[blockIdx.x] = v;
        __threadfence();                                  // publish partial
        unsigned int old = atomicAdd(&g_gal_count, 1u);
        is_last = (old == GAL_BLOCKS - 1);
    }
    __syncthreads();

    // ---- last block: final deterministic reduction in double ----
    if (is_last) {
        __threadfence();                                  // acquire partials
        const float4* __restrict__ p4 = (const float4*)g_gal_partials;
        double sd = 0.0;
        {                                                 // 1 float4 per thread
            const float4 p = p4[tid];
            sd += ((double)p.x + (double)p.y) + ((double)p.z + (double)p.w);
        }
        __shared__ double sh[256];
        sh[tid] = sd;
        __syncthreads();
        #pragma unroll
        for (int stride = 128; stride > 0; stride >>= 1) {
            if (tid < stride) sh[tid] += sh[tid + stride];
            __syncthreads();
        }
        if (tid == 0) {
            *out = (float)(sh[0] / (double)GAL_B);
            g_gal_count = 0;                              // reset for replay
        }
    }
}

// ---------------------------------------------------------------------------
// kernel_launch: inputs per metadata order:
//   d_in[0] = A        float32  [B*N*T]
//   d_in[1] = g        float32  [1]
//   d_in[2] = mel_lens int32    [B]
//   d_in[3] = seq_lens int32    [B]
// d_out: float32 [1]
// ---------------------------------------------------------------------------
extern "C" void kernel_launch(void* const* d_in, const int* in_sizes, int n_in,
                              void* d_out, int out_size)
{
    const float* A        = (const float*)d_in[0];
    const float* g        = (const float*)d_in[1];
    const int*   mel_lens = (const int*)d_in[2];
    const int*   seq_lens = (const int*)d_in[3];
    float*       out      = (float*)d_out;

    gal_main_kernel<<<GAL_BLOCKS, 256>>>(A, g, mel_lens, seq_lens, out);
}